// round 15
// baseline (speedup 1.0000x reference)
#include <cuda_runtime.h>
#include <cuda_bf16.h>
#include <math.h>
#include <stdint.h>

#define NB    512
#define VV    40
#define NODES (NB * VV)      // 20480
#define NF    32
#define EF    4
#define EMB   128
#define BIG_NEG -1000000.0f
#define EMAX  65536
#define DMAX  32

// column-pair index permutation: p = tg + 4h + 8k  ->  j = 2tg + h + 8k
#define PERM(p) ((((p) & 3) << 1) | (((p) >> 2) & 1) | ((p) & ~7))

// fast tanh: exact identity tanh(x) = 1 - 2/(e^{2x}+1); MUFU ex2 + rcp, ~1e-6 rel err
__device__ __forceinline__ float ftanh(float x) {
    float e = __expf(2.0f * x);
    return 1.0f - __fdividef(2.0f, e + 1.0f);
}

// ---- scratch (no allocation allowed) ----
__device__ float  g_M0[EMAX * EMB];
__device__ float  g_mem[EMAX * EMB];
__device__ float  g_memN[EMAX * EMB];
__device__ float2 g_UV[EMAX * EMB];     // (expU, V) per edge-ch; (L, tanhT) in readout
__device__ int    g_idx[EMAX * DMAX];
__device__ float  g_gs[NODES * EMB];
__device__ int    g_seg[NODES + 1];
__device__ float  g_P[NODES * 256];     // node projections: [0..127]=n-role, [128..255]=nb-role
// pre-packed B operands, (hi,lo) bf16-pair u64, permuted + XOR-swizzled:
__device__ __align__(16) uint2 g_B[2][256 * 64];   // set0 msg [Wa2|We2], set1 readout
__device__ __align__(16) uint2 g_Bpre[128 * 64];   // W_emb top half (pre stage-2, N=128)
__device__ __align__(16) uint2 g_Bnp[256 * 32];    // W_pre node part (K=32 pad 64, N=256)

__device__ __forceinline__ uint2 pack_hl(float x0, float x1) {
    __nv_bfloat16 h0 = __float2bfloat16(x0);
    __nv_bfloat16 h1 = __float2bfloat16(x1);
    __nv_bfloat16 l0 = __float2bfloat16(x0 - __bfloat162float(h0));
    __nv_bfloat16 l1 = __float2bfloat16(x1 - __bfloat162float(h1));
    uint32_t hi = (uint32_t)*(uint16_t*)&h0 | ((uint32_t)*(uint16_t*)&h1 << 16);
    uint32_t lo = (uint32_t)*(uint16_t*)&l0 | ((uint32_t)*(uint16_t*)&l1 << 16);
    return make_uint2(hi, lo);
}

__device__ __forceinline__ void mma16816(float* d, uint32_t a0, uint32_t a1,
                                         uint32_t a2, uint32_t a3,
                                         uint32_t b0, uint32_t b1) {
    asm volatile("mma.sync.aligned.m16n8k16.row.col.f32.bf16.bf16.f32 "
                 "{%0,%1,%2,%3}, {%4,%5,%6,%7}, {%8,%9}, {%0,%1,%2,%3};"
                 : "+f"(d[0]), "+f"(d[1]), "+f"(d[2]), "+f"(d[3])
                 : "r"(a0), "r"(a1), "r"(a2), "r"(a3), "r"(b0), "r"(b1));
}

// ---- init in-edge index table to -1 ----
__global__ void k_initidx(int n) {
    int i = blockIdx.x * blockDim.x + threadIdx.x;
    if (i < n) g_idx[i] = -1;
}

// ---- scatter in-edge lists ----
__global__ void k_scatter(const int* __restrict__ eb, const int* __restrict__ igeb,
                          const int* __restrict__ ige, int M, int D) {
    int i = blockIdx.x * blockDim.x + threadIdx.x;
    if (i < M) g_idx[igeb[i] * D + ige[i]] = eb[i];
}

// ---- pack all B operands ----
__global__ void k_packb(const float* __restrict__ W_pre,
                        const float* __restrict__ W_att, const float* __restrict__ W_emb,
                        const float* __restrict__ Wg_att, const float* __restrict__ Wg_emb) {
    int idx = blockIdx.x * 256 + threadIdx.x;   // 49152 total
    if (idx < 32768) {
        int set = idx >> 14;
        int rem = idx & 16383;
        int n = rem >> 6, p = rem & 63, kp = 2 * p;
        float x0, x1;
        if (set == 0) {
            if (n < 128) {
                x0 = W_att[(128 + kp) * EMB + n];
                x1 = W_att[(129 + kp) * EMB + n];
            } else {
                x0 = W_emb[(128 + kp) * EMB + (n - 128)];
                x1 = W_emb[(129 + kp) * EMB + (n - 128)];
            }
        } else {
            if (n < 128) {
                x0 = Wg_att[kp * EMB + n]       + Wg_att[(128 + kp) * EMB + n];
                x1 = Wg_att[(kp + 1) * EMB + n] + Wg_att[(129 + kp) * EMB + n];
            } else {
                x0 = Wg_emb[kp * EMB + (n - 128)];
                x1 = Wg_emb[(kp + 1) * EMB + (n - 128)];
            }
        }
        g_B[set][n * 64 + (PERM(p) ^ (4 * (n & 7)))] = pack_hl(x0, x1);
    } else if (idx < 40960) {
        int rem = idx - 32768;                   // W_emb top half, N=128, K=128
        int n = rem >> 6, p = rem & 63, kp = 2 * p;
        float x0 = W_emb[kp * EMB + n];
        float x1 = W_emb[(kp + 1) * EMB + n];
        g_Bpre[n * 64 + (PERM(p) ^ (4 * (n & 7)))] = pack_hl(x0, x1);
    } else {
        int rem = idx - 40960;                   // W_pre node part, N=256, K=32 pad 64
        int n = rem >> 5, p = rem & 31;
        float x0 = 0.f, x1 = 0.f;
        if (p < 16) {
            int kp = 2 * p;
            if (n < 128) {
                x0 = W_pre[kp * EMB + n];
                x1 = W_pre[(kp + 1) * EMB + n];
            } else {
                x0 = W_pre[(32 + kp) * EMB + (n - 128)];
                x1 = W_pre[(33 + kp) * EMB + (n - 128)];
            }
        }
        g_Bnp[n * 32 + (PERM(p) ^ (4 * (n & 7)))] = pack_hl(x0, x1);
    }
}

// ===== node projection: P = nodes[NODES x 32] @ Bnp -> [NODES x 256] ====
// only p<16 kpairs are real; MMA k-loop restricted to k<2 (covers exactly p<16)
#define NP_SMB_BYTES 65536   // Bs [256][32] uint2
#define NP_SMA_BYTES 32768   // As [128][32] uint2
#define NP_SM_TOTAL (NP_SMB_BYTES + NP_SMA_BYTES)

__global__ __launch_bounds__(256, 1)
void k_nodeproj_tc(const float* __restrict__ nodes) {
    extern __shared__ __align__(16) char sm[];
    uint2* Bs = (uint2*)sm;                     // [256][32]
    uint2* As = (uint2*)(sm + NP_SMB_BYTES);    // [128][32]
    const int tid = threadIdx.x;
    const int n0 = blockIdx.x * 128;

    {   // copy B: 8192 uint2 = 4096 uint4
        const uint4* s = (const uint4*)g_Bnp;
        uint4* d = (uint4*)Bs;
        #pragma unroll 4
        for (int i = tid; i < 4096; i += 256) d[i] = s[i];
    }
    {   // fill A: row = tid>>1; each half handles 8 real pairs
        int row = tid >> 1, h = tid & 1;
        int sw = 4 * (row & 7);
        uint2* arow = As + row * 32;
        const float* src = nodes + (size_t)(n0 + row) * NF;
        #pragma unroll
        for (int p = h * 8; p < h * 8 + 8; p += 2) {
            float4 f = *(const float4*)&src[2 * p];
            arow[PERM(p) ^ sw]     = pack_hl(f.x, f.y);
            arow[PERM(p + 1) ^ sw] = pack_hl(f.z, f.w);
        }
    }
    __syncthreads();

    const int wid = tid >> 5, lane = tid & 31;
    const int g = lane >> 2, tg = lane & 3;
    const int nU = wid * 16;

    #pragma unroll 1
    for (int mt = 0; mt < 8; mt++) {
        float d[4][4];
        #pragma unroll
        for (int a = 0; a < 4; a++)
            #pragma unroll
            for (int b = 0; b < 4; b++) d[a][b] = 0.0f;
        const int rowA = mt * 16 + g;
        #pragma unroll
        for (int k = 0; k < 2; k++) {           // p<16 only
            int jx = (2 * tg + 8 * k) ^ (4 * g);
            uint4 A1 = *(const uint4*)&As[rowA * 32 + jx];
            uint4 A2 = *(const uint4*)&As[(rowA + 8) * 32 + jx];
            #pragma unroll
            for (int nt = 0; nt < 4; nt++) {
                int nr = (nt < 2) ? (nU + nt * 8) : (128 + nU + (nt - 2) * 8);
                uint4 Bf = *(const uint4*)&Bs[(nr + g) * 32 + jx];
                mma16816(d[nt], A1.x, A2.x, A1.z, A2.z, Bf.x, Bf.z);
                mma16816(d[nt], A1.x, A2.x, A1.z, A2.z, Bf.y, Bf.w);
                mma16816(d[nt], A1.y, A2.y, A1.w, A2.w, Bf.x, Bf.z);
            }
        }
        int r0 = n0 + mt * 16 + g, r1 = r0 + 8;
        #pragma unroll
        for (int nt = 0; nt < 4; nt++) {
            int cc = (nt < 2) ? (nU + nt * 8 + tg * 2) : (128 + nU + (nt - 2) * 8 + tg * 2);
            *(float2*)&g_P[(size_t)r0 * 256 + cc] = make_float2(d[nt][0], d[nt][1]);
            *(float2*)&g_P[(size_t)r1 * 256 + cc] = make_float2(d[nt][2], d[nt][3]);
        }
    }
}

// ===== fused pre: e_emb = tanh(P1+P2+edge_term+b_pre); M0 = e_emb @ Wemb_top + b_emb;
//       mem1 = tanh(M0)  (step-1 closed form) =====
#define PR_SMB_BYTES 65536    // Bs [128][64] uint2
#define PR_SMA_BYTES 65536    // As [128][64] uint2
#define PR_SMX_BYTES 8192
#define PR_SM_TOTAL (PR_SMB_BYTES + PR_SMA_BYTES + PR_SMX_BYTES)

__global__ __launch_bounds__(256, 1)
void k_pre_tc(const float* __restrict__ edges,
              const float* __restrict__ W_pre, const float* __restrict__ b_pre,
              const float* __restrict__ b_emb,
              const int* __restrict__ eb_b, const int* __restrict__ eb_n,
              const int* __restrict__ eb_nb, int E) {
    extern __shared__ __align__(16) char sm[];
    uint2*  Bs   = (uint2*)sm;                            // [128][64]
    uint2*  As   = (uint2*)(sm + PR_SMB_BYTES);           // [128][64]
    char*   xtra = sm + PR_SMB_BYTES + PR_SMA_BYTES;
    int*    s_bn  = (int*)xtra;                           // [128]
    int*    s_bnb = (int*)(xtra + 512);                   // [128]
    float4* s_ed  = (float4*)(xtra + 1024);               // [128]
    float*  s_wp0 = (float*)(xtra + 3072);                // [128] x 4 rows
    float*  s_wp1 = s_wp0 + 128;
    float*  s_wp2 = s_wp0 + 256;
    float*  s_wp3 = s_wp0 + 384;
    float*  s_bp  = s_wp0 + 512;                          // b_pre
    float*  s_be  = s_wp0 + 640;                          // b_emb

    const int tid = threadIdx.x;
    const int e0 = blockIdx.x * 128;

    {   // copy B (W_emb top): 8192 uint2 = 4096 uint4
        const uint4* s = (const uint4*)g_Bpre;
        uint4* d = (uint4*)Bs;
        #pragma unroll 4
        for (int i = tid; i < 4096; i += 256) d[i] = s[i];
    }
    if (tid < 128) {
        s_wp0[tid] = W_pre[64 * EMB + tid];
        s_wp1[tid] = W_pre[65 * EMB + tid];
        s_wp2[tid] = W_pre[66 * EMB + tid];
        s_wp3[tid] = W_pre[67 * EMB + tid];
        s_bp[tid]  = b_pre[tid];
        s_be[tid]  = b_emb[tid];
        int e = e0 + tid;
        if (e < E) {
            int b = eb_b[e], n = eb_n[e], nb = eb_nb[e];
            s_bn[tid]  = (b * VV + n) * 256;
            s_bnb[tid] = (b * VV + nb) * 256 + 128;
            s_ed[tid]  = *(const float4*)&edges[(size_t)((b * VV + n) * VV + nb) * EF];
        } else {
            s_bn[tid] = -1;
        }
    }
    __syncthreads();

    // phase 1: each warp computes e_emb for 16 edges, 4 channels/lane, packs into As
    {
        const int wid = tid >> 5, lane = tid & 31;
        #pragma unroll 1
        for (int it = 0; it < 16; it++) {
            int r = wid * 16 + it;
            int sw = 4 * (r & 7);
            uint2* arow = As + r * 64;
            int p0 = 2 * lane;
            if (s_bn[r] >= 0) {
                float4 f1 = *(const float4*)&g_P[(size_t)s_bn[r]  + 4 * lane];
                float4 f2 = *(const float4*)&g_P[(size_t)s_bnb[r] + 4 * lane];
                float4 ed = s_ed[r];
                int c = 4 * lane;
                float4 w0 = *(const float4*)&s_wp0[c];
                float4 w1 = *(const float4*)&s_wp1[c];
                float4 w2 = *(const float4*)&s_wp2[c];
                float4 w3 = *(const float4*)&s_wp3[c];
                float4 bp = *(const float4*)&s_bp[c];
                float e0v = ftanh(f1.x + f2.x + ed.x * w0.x + ed.y * w1.x + ed.z * w2.x + ed.w * w3.x + bp.x);
                float e1v = ftanh(f1.y + f2.y + ed.x * w0.y + ed.y * w1.y + ed.z * w2.y + ed.w * w3.y + bp.y);
                float e2v = ftanh(f1.z + f2.z + ed.x * w0.z + ed.y * w1.z + ed.z * w2.z + ed.w * w3.z + bp.z);
                float e3v = ftanh(f1.w + f2.w + ed.x * w0.w + ed.y * w1.w + ed.z * w2.w + ed.w * w3.w + bp.w);
                arow[PERM(p0) ^ sw]     = pack_hl(e0v, e1v);
                arow[PERM(p0 + 1) ^ sw] = pack_hl(e2v, e3v);
            } else {
                uint2 z = make_uint2(0u, 0u);
                arow[PERM(p0) ^ sw]     = z;
                arow[PERM(p0 + 1) ^ sw] = z;
            }
        }
    }
    __syncthreads();

    // phase 2: MMA 128x128x128 -> M0, mem1
    const int wid = tid >> 5, lane = tid & 31;
    const int g = lane >> 2, tg = lane & 3;
    const int nU = wid * 16;

    #pragma unroll 1
    for (int mt = 0; mt < 8; mt++) {
        float d[2][4];
        #pragma unroll
        for (int a = 0; a < 2; a++)
            #pragma unroll
            for (int b = 0; b < 4; b++) d[a][b] = 0.0f;
        const int rowA = mt * 16 + g;
        #pragma unroll 1
        for (int k = 0; k < 8; k++) {
            int jx = (2 * tg + 8 * k) ^ (4 * g);
            uint4 A1 = *(const uint4*)&As[rowA * 64 + jx];
            uint4 A2 = *(const uint4*)&As[(rowA + 8) * 64 + jx];
            #pragma unroll
            for (int nt = 0; nt < 2; nt++) {
                uint4 Bf = *(const uint4*)&Bs[(nU + nt * 8 + g) * 64 + jx];
                mma16816(d[nt], A1.x, A2.x, A1.z, A2.z, Bf.x, Bf.z);
                mma16816(d[nt], A1.x, A2.x, A1.z, A2.z, Bf.y, Bf.w);
                mma16816(d[nt], A1.y, A2.y, A1.w, A2.w, Bf.x, Bf.z);
            }
        }
        int r0 = e0 + mt * 16 + g, r1 = r0 + 8;
        #pragma unroll
        for (int nt = 0; nt < 2; nt++) {
            int c = nU + nt * 8 + tg * 2;
            float be0 = s_be[c], be1 = s_be[c + 1];
            float m00 = d[nt][0] + be0, m01 = d[nt][1] + be1;
            float m10 = d[nt][2] + be0, m11 = d[nt][3] + be1;
            if (r0 < E) {
                *(float2*)&g_M0[(size_t)r0 * EMB + c]  = make_float2(m00, m01);
                *(float2*)&g_mem[(size_t)r0 * EMB + c] = make_float2(ftanh(m00), ftanh(m01));
            }
            if (r1 < E) {
                *(float2*)&g_M0[(size_t)r1 * EMB + c]  = make_float2(m10, m11);
                *(float2*)&g_mem[(size_t)r1 * EMB + c] = make_float2(ftanh(m10), ftanh(m11));
            }
        }
    }
}

// ============ tensor-core GEMM: [rows x 128] @ [128 x 256] (split bf16) ======
#define SMB_BYTES 131072      // B: [256][64] uint2
#define SMA_BYTES 65536       // A: [128][64] uint2
#define SM_TOTAL  (SMB_BYTES + SMA_BYTES)

__global__ __launch_bounds__(256, 1)
void k_gemm_tc(const float* __restrict__ src, const uint2* __restrict__ Bg,
               const float* __restrict__ ba, const float* __restrict__ bb,
               float2* __restrict__ out, int rows, int mode) {
    extern __shared__ __align__(16) char sm[];
    uint2* Bs = (uint2*)sm;                       // [256][64]
    uint2* As = (uint2*)(sm + SMB_BYTES);         // [128][64]
    const int tid = threadIdx.x;
    const int e0 = blockIdx.x * 128;

    {
        const uint4* s = (const uint4*)Bg;
        uint4* d = (uint4*)Bs;
        #pragma unroll 4
        for (int i = tid; i < 8192; i += 256) d[i] = s[i];
    }
    {
        int row = tid >> 1, half = tid & 1;
        int e = e0 + row;
        int sw = 4 * (row & 7);
        uint2* arow = As + row * 64;
        #pragma unroll 1
        for (int p = half * 32; p < half * 32 + 32; p += 2) {
            float4 f = make_float4(0.f, 0.f, 0.f, 0.f);
            if (e < rows) f = *(const float4*)&src[e * EMB + 2 * p];
            arow[PERM(p) ^ sw]     = pack_hl(f.x, f.y);
            arow[PERM(p + 1) ^ sw] = pack_hl(f.z, f.w);
        }
    }
    __syncthreads();

    const int wid = tid >> 5, lane = tid & 31;
    const int g = lane >> 2, tg = lane & 3;
    const int nU = wid * 16;

    float ba0[2], ba1[2], bb0[2], bb1[2];
    if (mode == 1) {
        #pragma unroll
        for (int nt = 0; nt < 2; nt++) {
            int c = nU + nt * 8 + tg * 2;
            ba0[nt] = ba[c]; ba1[nt] = ba[c + 1];
            bb0[nt] = bb[c]; bb1[nt] = bb[c + 1];
        }
    }

    #pragma unroll 1
    for (int mt = 0; mt < 8; mt++) {
        float d[4][4];
        #pragma unroll
        for (int a = 0; a < 4; a++)
            #pragma unroll
            for (int b = 0; b < 4; b++) d[a][b] = 0.0f;

        const int rowA = mt * 16 + g;
        #pragma unroll 1
        for (int k = 0; k < 8; k++) {
            int jx = (2 * tg + 8 * k) ^ (4 * g);
            uint4 A1 = *(const uint4*)&As[rowA * 64 + jx];
            uint4 A2 = *(const uint4*)&As[(rowA + 8) * 64 + jx];
            #pragma unroll
            for (int nt = 0; nt < 4; nt++) {
                int n0 = (nt < 2) ? (nU + nt * 8) : (128 + nU + (nt - 2) * 8);
                uint4 Bf = *(const uint4*)&Bs[(n0 + g) * 64 + jx];
                mma16816(d[nt], A1.x, A2.x, A1.z, A2.z, Bf.x, Bf.z);
                mma16816(d[nt], A1.x, A2.x, A1.z, A2.z, Bf.y, Bf.w);
                mma16816(d[nt], A1.y, A2.y, A1.w, A2.w, Bf.x, Bf.z);
            }
        }

        int r0 = e0 + mt * 16 + g, r1 = r0 + 8;
        #pragma unroll
        for (int nt = 0; nt < 2; nt++) {
            int c = nU + nt * 8 + tg * 2;
            float u0 = d[nt][0], u1 = d[nt][1], u2 = d[nt][2], u3 = d[nt][3];
            float v0 = d[nt + 2][0], v1 = d[nt + 2][1], v2 = d[nt + 2][2], v3 = d[nt + 2][3];
            float4 o0, o1;
            if (mode == 0) {
                o0 = make_float4(__expf(u0), v0, __expf(u1), v1);
                o1 = make_float4(__expf(u2), v2, __expf(u3), v3);
            } else {
                o0 = make_float4(u0 + ba0[nt], ftanh(v0 + bb0[nt]),
                                 u1 + ba1[nt], ftanh(v1 + bb1[nt]));
                o1 = make_float4(u2 + ba0[nt], ftanh(v2 + bb0[nt]),
                                 u3 + ba1[nt], ftanh(v3 + bb1[nt]));
            }
            if (r0 < rows) *(float4*)&out[(size_t)r0 * EMB + c] = o0;
            if (r1 < rows) *(float4*)&out[(size_t)r1 * EMB + c] = o1;
        }
    }
}

// ---- per-step combine ----
__global__ void k_combine(float* __restrict__ dst, int D, int E) {
    const int e = blockIdx.x;
    const int tid = threadIdx.x;
    __shared__ int js[DMAX];
    if (tid < D) js[tid] = g_idx[e * D + tid];
    __syncthreads();

    float m0 = g_M0[e * EMB + tid];
    float ssum = 0.0f, acc = 0.0f;
    int cnt = 0;
    for (int d = 0; d < D; d++) {
        int j = js[d];
        if (j >= 0) {
            float2 uv = g_UV[j * EMB + tid];
            ssum += uv.x;
            acc  += uv.x * ftanh(m0 + uv.y);
            cnt++;
        }
    }
    dst[e * EMB + tid] = cnt ? __fdividef(acc, ssum) : ftanh(m0);
}

// ---- segment boundaries ----
__global__ void k_segbounds(const int* __restrict__ eb_b, const int* __restrict__ eb_n, int E) {
    int e = blockIdx.x * blockDim.x + threadIdx.x;
    if (e >= E) return;
    int k  = eb_b[e] * VV + eb_n[e];
    int kp = (e == 0) ? -1 : (eb_b[e - 1] * VV + eb_n[e - 1]);
    for (int v = kp + 1; v <= k; v++) g_seg[v] = e;
    if (e == E - 1) for (int v = k + 1; v <= NODES; v++) g_seg[v] = E;
}

// ---- segment sum ----
__global__ void k_segsum(const float* __restrict__ mem) {
    const int node = blockIdx.x;
    const int tid = threadIdx.x;
    int lo = g_seg[node], hi = g_seg[node + 1];
    float acc = 0.0f;
    for (int e = lo; e < hi; e++) acc += mem[e * EMB + tid];
    g_gs[node * EMB + tid] = acc;
}

// ---- readout softmax + final projection ----
__global__ void k_rsoft(const float* __restrict__ node_mask,
                        const float* __restrict__ W_out, const float* __restrict__ b_out,
                        float* __restrict__ out) {
    const int n = blockIdx.x;
    const int tid = threadIdx.x;
    __shared__ float s_msk[VV];
    __shared__ float ge[EMB];
    __shared__ int   s_any;
    if (tid == 0) s_any = 0;
    __syncthreads();
    if (tid < VV) {
        s_msk[tid] = node_mask[n * VV + tid];
        if (s_msk[tid] > 0.5f) atomicOr(&s_any, 1);
    }
    __syncthreads();
    const int any = s_any;

    const float2* LT = g_UV + (size_t)n * VV * EMB;
    float mx = -1e30f;
    for (int v = 0; v < VV; v++) {
        if (!any || s_msk[v] > 0.5f) {
            float l = LT[v * EMB + tid].x;
            mx = fmaxf(mx, l);
        }
    }
    float ssum = 0.0f, acc = 0.0f;
    for (int v = 0; v < VV; v++) {
        if (!any || s_msk[v] > 0.5f) {
            float2 lt = LT[v * EMB + tid];
            float w = __expf(lt.x - mx);
            ssum += w;
            acc  += w * lt.y;
        }
    }
    ge[tid] = __fdividef(acc, ssum);
    __syncthreads();

    float o = b_out[tid];
    #pragma unroll 4
    for (int k = 0; k < EMB; k++) o += ge[k] * W_out[k * EMB + tid];
    out[n * EMB + tid] = o;
}

extern "C" void kernel_launch(void* const* d_in, const int* in_sizes, int n_in,
                              void* d_out, int out_size) {
    const float* nodes     = (const float*)d_in[0];
    const float* edges     = (const float*)d_in[1];
    const float* W_pre     = (const float*)d_in[2];
    const float* b_pre     = (const float*)d_in[3];
    const float* W_att     = (const float*)d_in[4];
    const float* W_emb     = (const float*)d_in[6];
    const float* b_emb     = (const float*)d_in[7];
    const float* Wg_att    = (const float*)d_in[8];
    const float* bg_att    = (const float*)d_in[9];
    const float* Wg_emb    = (const float*)d_in[10];
    const float* bg_emb    = (const float*)d_in[11];
    const float* W_out     = (const float*)d_in[12];
    const float* b_out     = (const float*)d_in[13];
    const float* node_mask = (const float*)d_in[15];
    const int*   eb_b      = (const int*)d_in[16];
    const int*   eb_n      = (const int*)d_in[17];
    const int*   eb_nb     = (const int*)d_in[18];
    const int*   in_eb     = (const int*)d_in[19];
    const int*   in_igeb   = (const int*)d_in[20];
    const int*   in_ige    = (const int*)d_in[21];

    const int E = in_sizes[16];
    const int D = in_sizes[14] / E;
    const int M = in_sizes[19];

    cudaFuncSetAttribute(k_gemm_tc, cudaFuncAttributeMaxDynamicSharedMemorySize, SM_TOTAL);
    cudaFuncSetAttribute(k_pre_tc, cudaFuncAttributeMaxDynamicSharedMemorySize, PR_SM_TOTAL);
    cudaFuncSetAttribute(k_nodeproj_tc, cudaFuncAttributeMaxDynamicSharedMemorySize, NP_SM_TOTAL);

    float *memA, *memB;
    cudaGetSymbolAddress((void**)&memA, g_mem);
    cudaGetSymbolAddress((void**)&memB, g_memN);
    uint2* bpk;
    cudaGetSymbolAddress((void**)&bpk, g_B);
    float2* uv;
    cudaGetSymbolAddress((void**)&uv, g_UV);
    float* gs;
    cudaGetSymbolAddress((void**)&gs, g_gs);

    k_initidx<<<(E * D + 255) / 256, 256>>>(E * D);
    k_scatter<<<(M + 255) / 256, 256>>>(in_eb, in_igeb, in_ige, M, D);
    k_packb<<<192, 256>>>(W_pre, W_att, W_emb, Wg_att, Wg_emb);
    k_nodeproj_tc<<<NODES / 128, 256, NP_SM_TOTAL>>>(nodes);
    k_pre_tc<<<(E + 127) / 128, 256, PR_SM_TOTAL>>>(edges, W_pre, b_pre, b_emb,
                                                    eb_b, eb_n, eb_nb, E);

    // step 1 closed-form (mem1 = tanh(M0)); run steps 2..3
    float* src = memA;
    float* dst = memB;
    for (int s = 0; s < 2; s++) {
        k_gemm_tc<<<(E + 127) / 128, 256, SM_TOTAL>>>(src, bpk, b_out, b_out, uv, E, 0);
        k_combine<<<E, 128>>>(dst, D, E);
        float* t = src; src = dst; dst = t;
    }

    k_segbounds<<<(E + 255) / 256, 256>>>(eb_b, eb_n, E);
    k_segsum<<<NODES, 128>>>(src);
    k_gemm_tc<<<NODES / 128, 256, SM_TOTAL>>>(gs, bpk + 256 * 64, bg_att, bg_emb, uv, NODES, 1);
    k_rsoft<<<NB, 128>>>(node_mask, W_out, b_out, (float*)d_out);
}